// round 1
// baseline (speedup 1.0000x reference)
#include <cuda_runtime.h>
#include <math.h>

#define BB   8192
#define SS   512
#define KK   8
#define HH   512
#define NC   8704          // S*(2K+1)
#define EPSK 1e-6f

// scratch (static device globals — no allocations)
__device__ float g_hid[(size_t)BB * HH];   // 16 MB
__device__ float g_net[(size_t)BB * NC];   // 285 MB

// ---------------------------------------------------------------------------
// C = tanh(A @ B + bias)   A: MxK row-major (lda), B: KxN row-major, C: MxN
// 128x128 tile, Kt=8, 256 threads, 8x8 per-thread micro-tile, double-buffered.
// All dims are multiples of tile sizes — no guards.
// ---------------------------------------------------------------------------
template <bool SUB_HALF>
__global__ __launch_bounds__(256, 2)
void sgemm_tanh_kernel(const float* __restrict__ A, const float* __restrict__ Bm,
                       const float* __restrict__ bias, float* __restrict__ C,
                       int M, int N, int K, int lda)
{
    __shared__ float As[2][8][128];   // [k][m]
    __shared__ float Bs[2][8][128];   // [k][n]

    const int tid = threadIdx.x;
    const int tx  = tid & 15;         // 16 col-groups
    const int ty  = tid >> 4;         // 16 row-groups
    const int mBase = blockIdx.y * 128;
    const int nBase = blockIdx.x * 128;

    // A tile loader: 128 rows x 8 k, one float4 per thread
    const int arow = tid >> 1;
    const int acol = (tid & 1) << 2;
    // B tile loader: 8 rows x 128 cols, one float4 per thread
    const int brow = tid >> 5;
    const int bcol = (tid & 31) << 2;

    const float* Aptr = A  + (size_t)(mBase + arow) * lda + acol;
    const float* Bptr = Bm + (size_t)brow * N + nBase + bcol;

    float acc[8][8];
    #pragma unroll
    for (int i = 0; i < 8; i++)
        #pragma unroll
        for (int j = 0; j < 8; j++) acc[i][j] = 0.f;

    float4 pA = *(const float4*)Aptr;
    if (SUB_HALF) { pA.x -= 0.5f; pA.y -= 0.5f; pA.z -= 0.5f; pA.w -= 0.5f; }
    float4 pB = *(const float4*)Bptr;

    As[0][acol + 0][arow] = pA.x;
    As[0][acol + 1][arow] = pA.y;
    As[0][acol + 2][arow] = pA.z;
    As[0][acol + 3][arow] = pA.w;
    *(float4*)&Bs[0][brow][bcol] = pB;
    __syncthreads();

    int buf = 0;
    const int nT = K >> 3;
    for (int t = 0; t < nT; t++) {
        if (t + 1 < nT) {
            pA = *(const float4*)(Aptr + (t + 1) * 8);
            if (SUB_HALF) { pA.x -= 0.5f; pA.y -= 0.5f; pA.z -= 0.5f; pA.w -= 0.5f; }
            pB = *(const float4*)(Bptr + (size_t)(t + 1) * 8 * N);
        }
        #pragma unroll
        for (int kt = 0; kt < 8; kt++) {
            float4 a0 = *(const float4*)&As[buf][kt][ty * 4];
            float4 a1 = *(const float4*)&As[buf][kt][ty * 4 + 64];
            float4 b0 = *(const float4*)&Bs[buf][kt][tx * 4];
            float4 b1 = *(const float4*)&Bs[buf][kt][tx * 4 + 64];
            float a[8] = {a0.x, a0.y, a0.z, a0.w, a1.x, a1.y, a1.z, a1.w};
            float b[8] = {b0.x, b0.y, b0.z, b0.w, b1.x, b1.y, b1.z, b1.w};
            #pragma unroll
            for (int i = 0; i < 8; i++)
                #pragma unroll
                for (int j = 0; j < 8; j++)
                    acc[i][j] = fmaf(a[i], b[j], acc[i][j]);
        }
        if (t + 1 < nT) {
            const int nb = buf ^ 1;
            As[nb][acol + 0][arow] = pA.x;
            As[nb][acol + 1][arow] = pA.y;
            As[nb][acol + 2][arow] = pA.z;
            As[nb][acol + 3][arow] = pA.w;
            *(float4*)&Bs[nb][brow][bcol] = pB;
            __syncthreads();
            buf = nb;
        }
    }

    float bb[8];
    *(float4*)&bb[0] = *(const float4*)&bias[nBase + tx * 4];
    *(float4*)&bb[4] = *(const float4*)&bias[nBase + 64 + tx * 4];

    #pragma unroll
    for (int i = 0; i < 8; i++) {
        const int row = mBase + ((i < 4) ? (ty * 4 + i) : (64 + ty * 4 + i - 4));
        float4 o0, o1;
        o0.x = tanhf(acc[i][0] + bb[0]);
        o0.y = tanhf(acc[i][1] + bb[1]);
        o0.z = tanhf(acc[i][2] + bb[2]);
        o0.w = tanhf(acc[i][3] + bb[3]);
        o1.x = tanhf(acc[i][4] + bb[4]);
        o1.y = tanhf(acc[i][5] + bb[5]);
        o1.z = tanhf(acc[i][6] + bb[6]);
        o1.w = tanhf(acc[i][7] + bb[7]);
        float* Crow = C + (size_t)row * N + nBase;
        *(float4*)&Crow[tx * 4]      = o0;
        *(float4*)&Crow[64 + tx * 4] = o1;
    }
}

// ---------------------------------------------------------------------------
// Spline epilogue: one block per batch row b (512 threads, one per s).
// Reads net[b, s, 0:17], computes phi_b and the per-(b,s) log term;
// block-reduces the log sum; copies x_a into the output.
// ---------------------------------------------------------------------------
__global__ __launch_bounds__(512)
void spline_epilogue_kernel(const float* __restrict__ x_input,
                            const float* __restrict__ log_density,
                            const float* __restrict__ net,
                            float* __restrict__ out)
{
    const int b = blockIdx.x;
    const int s = threadIdx.x;

    const float* np = net + (size_t)b * NC + s * 17;
    float v[17];
    #pragma unroll
    for (int j = 0; j < 17; j++) v[j] = np[j];

    // softmax over w_raw = v[9..16]
    float m = v[9];
    #pragma unroll
    for (int j = 10; j < 17; j++) m = fmaxf(m, v[j]);
    float w[8];
    float wsum = 0.f;
    #pragma unroll
    for (int j = 0; j < 8; j++) { w[j] = __expf(v[9 + j] - m); wsum += w[j]; }
    const float winv = 1.f / wsum;
    #pragma unroll
    for (int j = 0; j < 8; j++) w[j] *= winv;

    // h_norm
    float eh[9];
    #pragma unroll
    for (int j = 0; j < 9; j++) eh[j] = __expf(v[j]);
    float denom = 0.f;
    #pragma unroll
    for (int i = 0; i < 8; i++) denom += 0.5f * w[i] * (eh[i] + eh[i + 1]);
    const float dinv = 1.f / denom;
    float h[9];
    #pragma unroll
    for (int i = 0; i < 9; i++) h[i] = eh[i] * dinv;

    const float xa = x_input[(size_t)b * (2 * SS) + s];
    const float xb = x_input[(size_t)b * (2 * SS) + SS + s];

    // bin index: count knots < xb, knots = [-eps, cumsum(w)]
    int cnt = (-EPSK < xb) ? 1 : 0;
    float cs = 0.f;
    #pragma unroll
    for (int i = 0; i < 8; i++) { cs += w[i]; cnt += (cs < xb) ? 1 : 0; }
    int k = cnt - 1;
    k = k < 0 ? 0 : (k > 7 ? 7 : k);

    // gather bin parameters (unrolled predicated selection; no local-mem arrays)
    float xk = 0.f, pk = 0.f, wk = 0.f, hk = 0.f, hk1 = 0.f;
    #pragma unroll
    for (int i = 0; i < 8; i++) {
        const float area = 0.5f * w[i] * (h[i] + h[i + 1]);
        if (i < k)  { xk += w[i]; pk += area; }
        if (i == k) { wk = w[i]; hk = h[i]; hk1 = h[i + 1]; }
    }
    if (k == 0) xk = -EPSK;

    const float alpha = (xb - xk) / wk;
    const float phib  = pk + alpha * hk * wk + 0.5f * alpha * alpha * (hk1 - hk) * wk;
    const float lt    = __logf(fmaf(alpha, (hk1 - hk), hk));

    out[(size_t)b * (2 * SS) + s]      = xa;
    out[(size_t)b * (2 * SS) + SS + s] = phib;

    // block-reduce the log terms
    __shared__ float red[16];
    float sum = lt;
    #pragma unroll
    for (int o = 16; o > 0; o >>= 1) sum += __shfl_xor_sync(0xffffffffu, sum, o);
    const int lane = s & 31, wid = s >> 5;
    if (lane == 0) red[wid] = sum;
    __syncthreads();
    if (s < 16) {
        float t = red[s];
        #pragma unroll
        for (int o = 8; o > 0; o >>= 1) t += __shfl_xor_sync(0xffffu, t, o);
        if (s == 0) out[(size_t)BB * (2 * SS) + b] = log_density[b] - t;
    }
}

// ---------------------------------------------------------------------------
extern "C" void kernel_launch(void* const* d_in, const int* in_sizes, int n_in,
                              void* d_out, int out_size)
{
    const float* x   = (const float*)d_in[0];  // (B, 2S)
    const float* ld  = (const float*)d_in[1];  // (B, 1)
    const float* W1  = (const float*)d_in[2];  // (S, H)
    const float* b1  = (const float*)d_in[3];  // (H,)
    const float* W2  = (const float*)d_in[4];  // (H, S*(2K+1))
    const float* b2  = (const float*)d_in[5];  // (S*(2K+1),)
    float* out = (float*)d_out;

    float *hid, *net;
    cudaGetSymbolAddress((void**)&hid, g_hid);
    cudaGetSymbolAddress((void**)&net, g_net);

    // hid = tanh((x_a - 0.5) @ W1 + b1):  M=8192, N=512, K=512, lda=1024
    sgemm_tanh_kernel<true><<<dim3(HH / 128, BB / 128), 256>>>(
        x, W1, b1, hid, BB, HH, SS, 2 * SS);

    // net = tanh(hid @ W2 + b2):  M=8192, N=8704, K=512
    sgemm_tanh_kernel<false><<<dim3(NC / 128, BB / 128), 256>>>(
        hid, W2, b2, net, BB, NC, HH, HH);

    // spline evaluation + log-det reduction + x_a passthrough
    spline_epilogue_kernel<<<BB, 512>>>(x, ld, net, out);
}